// round 1
// baseline (speedup 1.0000x reference)
#include <cuda_runtime.h>

// Outputs, flattened in tuple order into d_out (float32):
//   [0,   3N)  new_o   (N,3)
//   [3N,  6N)  new_d   (N,3)
//   [6N, 15N)  R       (N,3,3) row-major
//   [15N,18N)  t       (N,3)

__global__ void __launch_bounds__(256)
camera_extrinsics_kernel(const int* __restrict__ idx,
                         const float* __restrict__ o,
                         const float* __restrict__ d,
                         const float* __restrict__ rot,
                         const float* __restrict__ trans,
                         float* __restrict__ out,
                         int n)
{
    int b = blockIdx.x * blockDim.x + threadIdx.x;
    if (b >= n) return;

    const int im = idx[b];

    const float rx = __ldg(rot + 3 * im + 0);
    const float ry = __ldg(rot + 3 * im + 1);
    const float rz = __ldg(rot + 3 * im + 2);
    const float tx = __ldg(trans + 3 * im + 0);
    const float ty = __ldg(trans + 3 * im + 1);
    const float tz = __ldg(trans + 3 * im + 2);

    const float th2 = rx * rx + ry * ry + rz * rz;

    // sin_c = sin(th)/th, cos_c = (1-cos(th))/th^2.
    // For th < 0.05 the truncated series is exact to fp32 ulp (error ~ th^6/5040).
    float A = 1.0f - (th2 * (1.0f / 6.0f)) * (1.0f - th2 * (1.0f / 20.0f));
    float B = 0.5f - (th2 * (1.0f / 24.0f)) * (1.0f - th2 * (1.0f / 30.0f));
    if (th2 > 0.0025f) {  // th > 0.05 — not hit on this data, correctness guard only
        float th = sqrtf(th2);
        float s, c;
        __sincosf(th, &s, &c);
        A = s / th;
        B = (1.0f - c) / th2;
    }

    // R = I + A*K + B*(r r^T - th2*I)   (since K^2 = r r^T - th2*I)
    const float Brx = B * rx, Bry = B * ry, Brz = B * rz;
    const float R00 = 1.0f + (Brx * rx - B * th2);
    const float R11 = 1.0f + (Bry * ry - B * th2);
    const float R22 = 1.0f + (Brz * rz - B * th2);
    const float Bxy = Brx * ry;
    const float Bxz = Brx * rz;
    const float Byz = Bry * rz;
    const float Az = A * rz, Ay = A * ry, Ax = A * rx;
    const float R01 = Bxy - Az;
    const float R10 = Bxy + Az;
    const float R02 = Bxz + Ay;
    const float R20 = Bxz - Ay;
    const float R12 = Byz - Ax;
    const float R21 = Byz + Ax;

    const float ox = o[3 * b + 0], oy = o[3 * b + 1], oz = o[3 * b + 2];
    const float dx = d[3 * b + 0], dy = d[3 * b + 1], dz = d[3 * b + 2];

    const float no0 = fmaf(R00, ox, fmaf(R01, oy, fmaf(R02, oz, tx)));
    const float no1 = fmaf(R10, ox, fmaf(R11, oy, fmaf(R12, oz, ty)));
    const float no2 = fmaf(R20, ox, fmaf(R21, oy, fmaf(R22, oz, tz)));
    const float nd0 = fmaf(R00, dx, fmaf(R01, dy, R02 * dz));
    const float nd1 = fmaf(R10, dx, fmaf(R11, dy, R12 * dz));
    const float nd2 = fmaf(R20, dx, fmaf(R21, dy, R22 * dz));

    const long long N = n;
    float* __restrict__ out_no = out;
    float* __restrict__ out_nd = out + 3 * N;
    float* __restrict__ out_R  = out + 6 * N;
    float* __restrict__ out_t  = out + 15 * N;

    out_no[3 * b + 0] = no0;
    out_no[3 * b + 1] = no1;
    out_no[3 * b + 2] = no2;

    out_nd[3 * b + 0] = nd0;
    out_nd[3 * b + 1] = nd1;
    out_nd[3 * b + 2] = nd2;

    float* Rw = out_R + 9LL * b;
    Rw[0] = R00; Rw[1] = R01; Rw[2] = R02;
    Rw[3] = R10; Rw[4] = R11; Rw[5] = R12;
    Rw[6] = R20; Rw[7] = R21; Rw[8] = R22;

    out_t[3 * b + 0] = tx;
    out_t[3 * b + 1] = ty;
    out_t[3 * b + 2] = tz;
}

extern "C" void kernel_launch(void* const* d_in, const int* in_sizes, int n_in,
                              void* d_out, int out_size) {
    const int*   i_ptr = (const int*)d_in[0];
    const float* o_ptr = (const float*)d_in[1];
    const float* d_ptr = (const float*)d_in[2];
    const float* rot   = (const float*)d_in[3];
    const float* trans = (const float*)d_in[4];
    float* out = (float*)d_out;

    const int n = in_sizes[0];
    const int threads = 256;
    const int blocks = (n + threads - 1) / threads;
    camera_extrinsics_kernel<<<blocks, threads>>>(i_ptr, o_ptr, d_ptr, rot, trans, out, n);
}

// round 2
// speedup vs baseline: 1.1947x; 1.1947x over previous
#include <cuda_runtime.h>

// Outputs, flattened in tuple order into d_out (float32):
//   [0,   3N)  new_o   (N,3)
//   [3N,  6N)  new_d   (N,3)
//   [6N, 15N)  R       (N,3,3) row-major
//   [15N,18N)  t       (N,3)

#define MAX_SMEM_IMAGES 1024
#define TPB 128
#define RAYS_PER_THREAD 4

__device__ __forceinline__ void rodrigues_AB(float th2, float& A, float& B) {
    // sin_c = sin(th)/th, cos_c = (1-cos(th))/th^2; series exact to fp32 ulp for th<0.05
    A = 1.0f - (th2 * (1.0f / 6.0f)) * (1.0f - th2 * (1.0f / 20.0f));
    B = 0.5f - (th2 * (1.0f / 24.0f)) * (1.0f - th2 * (1.0f / 30.0f));
    if (th2 > 0.0025f) {   // correctness guard; never hit on this data
        float th = sqrtf(th2);
        float s, c;
        __sincosf(th, &s, &c);
        A = s / th;
        B = (1.0f - c) / th2;
    }
}

__global__ void __launch_bounds__(TPB)
camx_vec_kernel(const int* __restrict__ idx,
                const float* __restrict__ o,
                const float* __restrict__ d,
                const float* __restrict__ rot,
                const float* __restrict__ trans,
                float* __restrict__ out,
                int n, int n_img)
{
    __shared__ float s_rot[3 * MAX_SMEM_IMAGES];
    __shared__ float s_trans[3 * MAX_SMEM_IMAGES];

    // Cooperative coalesced fill of the gather tables (amortized over 512 rays/block)
    const int nr3 = 3 * n_img;
    for (int j = threadIdx.x; j < nr3; j += TPB) {
        s_rot[j]   = rot[j];
        s_trans[j] = trans[j];
    }
    __syncthreads();

    const long long tno = (long long)blockIdx.x * TPB + threadIdx.x;
    const long long b0 = tno * RAYS_PER_THREAD;
    if (b0 >= n) return;

    const long long N = n;
    float* __restrict__ out_no = out;
    float* __restrict__ out_nd = out + 3 * N;
    float* __restrict__ out_R  = out + 6 * N;
    float* __restrict__ out_t  = out + 15 * N;

    if (b0 + RAYS_PER_THREAD <= n) {
        // ---------------- fast vectorized path ----------------
        const int4 iv = *reinterpret_cast<const int4*>(idx + b0);
        const int im[4] = { iv.x, iv.y, iv.z, iv.w };

        float Rf[36];   // 4 rays x 9
        float tx[4], ty[4], tz[4];

        #pragma unroll
        for (int j = 0; j < 4; j++) {
            const int base = 3 * im[j];
            const float rx = s_rot[base + 0];
            const float ry = s_rot[base + 1];
            const float rz = s_rot[base + 2];
            tx[j] = s_trans[base + 0];
            ty[j] = s_trans[base + 1];
            tz[j] = s_trans[base + 2];

            const float th2 = rx * rx + ry * ry + rz * rz;
            float A, B;
            rodrigues_AB(th2, A, B);

            const float Brx = B * rx, Bry = B * ry, Brz = B * rz;
            const float Bt = B * th2;
            const float Bxy = Brx * ry, Bxz = Brx * rz, Byz = Bry * rz;
            const float Ax = A * rx, Ay = A * ry, Az = A * rz;
            Rf[9*j+0] = 1.0f + (Brx * rx - Bt);
            Rf[9*j+1] = Bxy - Az;
            Rf[9*j+2] = Bxz + Ay;
            Rf[9*j+3] = Bxy + Az;
            Rf[9*j+4] = 1.0f + (Bry * ry - Bt);
            Rf[9*j+5] = Byz - Ax;
            Rf[9*j+6] = Bxz - Ay;
            Rf[9*j+7] = Byz + Ax;
            Rf[9*j+8] = 1.0f + (Brz * rz - Bt);
        }

        // ---- new_o = R @ o + t  (12 floats in = 3 float4; 12 out = 3 float4) ----
        {
            const float4* o4 = reinterpret_cast<const float4*>(o + 3 * b0);
            const float4 a = o4[0], bq = o4[1], c = o4[2];
            const float x[4] = { a.x, a.w, bq.z, c.y };
            const float y[4] = { a.y, bq.x, bq.w, c.z };
            const float z[4] = { a.z, bq.y, c.x, c.w };
            float v[12];
            #pragma unroll
            for (int j = 0; j < 4; j++) {
                v[3*j+0] = fmaf(Rf[9*j+0], x[j], fmaf(Rf[9*j+1], y[j], fmaf(Rf[9*j+2], z[j], tx[j])));
                v[3*j+1] = fmaf(Rf[9*j+3], x[j], fmaf(Rf[9*j+4], y[j], fmaf(Rf[9*j+5], z[j], ty[j])));
                v[3*j+2] = fmaf(Rf[9*j+6], x[j], fmaf(Rf[9*j+7], y[j], fmaf(Rf[9*j+8], z[j], tz[j])));
            }
            float4* w = reinterpret_cast<float4*>(out_no + 3 * b0);
            w[0] = make_float4(v[0], v[1], v[2], v[3]);
            w[1] = make_float4(v[4], v[5], v[6], v[7]);
            w[2] = make_float4(v[8], v[9], v[10], v[11]);
        }

        // ---- new_d = R @ d ----
        {
            const float4* d4 = reinterpret_cast<const float4*>(d + 3 * b0);
            const float4 a = d4[0], bq = d4[1], c = d4[2];
            const float x[4] = { a.x, a.w, bq.z, c.y };
            const float y[4] = { a.y, bq.x, bq.w, c.z };
            const float z[4] = { a.z, bq.y, c.x, c.w };
            float v[12];
            #pragma unroll
            for (int j = 0; j < 4; j++) {
                v[3*j+0] = fmaf(Rf[9*j+0], x[j], fmaf(Rf[9*j+1], y[j], Rf[9*j+2] * z[j]));
                v[3*j+1] = fmaf(Rf[9*j+3], x[j], fmaf(Rf[9*j+4], y[j], Rf[9*j+5] * z[j]));
                v[3*j+2] = fmaf(Rf[9*j+6], x[j], fmaf(Rf[9*j+7], y[j], Rf[9*j+8] * z[j]));
            }
            float4* w = reinterpret_cast<float4*>(out_nd + 3 * b0);
            w[0] = make_float4(v[0], v[1], v[2], v[3]);
            w[1] = make_float4(v[4], v[5], v[6], v[7]);
            w[2] = make_float4(v[8], v[9], v[10], v[11]);
        }

        // ---- R: 36 floats = 9 float4 ----
        {
            float4* w = reinterpret_cast<float4*>(out_R + 9 * b0);
            #pragma unroll
            for (int q = 0; q < 9; q++)
                w[q] = make_float4(Rf[4*q+0], Rf[4*q+1], Rf[4*q+2], Rf[4*q+3]);
        }

        // ---- t: 12 floats = 3 float4 ----
        {
            float4* w = reinterpret_cast<float4*>(out_t + 3 * b0);
            w[0] = make_float4(tx[0], ty[0], tz[0], tx[1]);
            w[1] = make_float4(ty[1], tz[1], tx[2], ty[2]);
            w[2] = make_float4(tz[2], tx[3], ty[3], tz[3]);
        }
    } else {
        // ---------------- scalar tail ----------------
        for (long long b = b0; b < n; b++) {
            const int imb = idx[b];
            const float rx = s_rot[3*imb+0], ry = s_rot[3*imb+1], rz = s_rot[3*imb+2];
            const float txs = s_trans[3*imb+0], tys = s_trans[3*imb+1], tzs = s_trans[3*imb+2];
            const float th2 = rx*rx + ry*ry + rz*rz;
            float A, B;
            rodrigues_AB(th2, A, B);
            const float Brx = B*rx, Bry = B*ry, Brz = B*rz, Bt = B*th2;
            const float R00 = 1.0f + (Brx*rx - Bt), R11 = 1.0f + (Bry*ry - Bt), R22 = 1.0f + (Brz*rz - Bt);
            const float Bxy = Brx*ry, Bxz = Brx*rz, Byz = Bry*rz;
            const float Ax = A*rx, Ay = A*ry, Az = A*rz;
            const float R01 = Bxy - Az, R10 = Bxy + Az, R02 = Bxz + Ay;
            const float R20 = Bxz - Ay, R12 = Byz - Ax, R21 = Byz + Ax;
            const float ox = o[3*b+0], oy = o[3*b+1], oz = o[3*b+2];
            const float dx = d[3*b+0], dy = d[3*b+1], dz = d[3*b+2];
            out_no[3*b+0] = fmaf(R00, ox, fmaf(R01, oy, fmaf(R02, oz, txs)));
            out_no[3*b+1] = fmaf(R10, ox, fmaf(R11, oy, fmaf(R12, oz, tys)));
            out_no[3*b+2] = fmaf(R20, ox, fmaf(R21, oy, fmaf(R22, oz, tzs)));
            out_nd[3*b+0] = fmaf(R00, dx, fmaf(R01, dy, R02 * dz));
            out_nd[3*b+1] = fmaf(R10, dx, fmaf(R11, dy, R12 * dz));
            out_nd[3*b+2] = fmaf(R20, dx, fmaf(R21, dy, R22 * dz));
            float* Rw = out_R + 9 * b;
            Rw[0]=R00; Rw[1]=R01; Rw[2]=R02; Rw[3]=R10; Rw[4]=R11; Rw[5]=R12; Rw[6]=R20; Rw[7]=R21; Rw[8]=R22;
            out_t[3*b+0] = txs; out_t[3*b+1] = tys; out_t[3*b+2] = tzs;
        }
    }
}

// Fallback for n_img > MAX_SMEM_IMAGES: scalar, global gathers (round-1 kernel).
__global__ void __launch_bounds__(256)
camx_scalar_kernel(const int* __restrict__ idx,
                   const float* __restrict__ o,
                   const float* __restrict__ d,
                   const float* __restrict__ rot,
                   const float* __restrict__ trans,
                   float* __restrict__ out,
                   int n)
{
    int b = blockIdx.x * blockDim.x + threadIdx.x;
    if (b >= n) return;
    const int im = idx[b];
    const float rx = __ldg(rot + 3*im+0), ry = __ldg(rot + 3*im+1), rz = __ldg(rot + 3*im+2);
    const float tx = __ldg(trans + 3*im+0), ty = __ldg(trans + 3*im+1), tz = __ldg(trans + 3*im+2);
    const float th2 = rx*rx + ry*ry + rz*rz;
    float A, B;
    rodrigues_AB(th2, A, B);
    const float Brx = B*rx, Bry = B*ry, Brz = B*rz, Bt = B*th2;
    const float R00 = 1.0f + (Brx*rx - Bt), R11 = 1.0f + (Bry*ry - Bt), R22 = 1.0f + (Brz*rz - Bt);
    const float Bxy = Brx*ry, Bxz = Brx*rz, Byz = Bry*rz;
    const float Ax = A*rx, Ay = A*ry, Az = A*rz;
    const float R01 = Bxy - Az, R10 = Bxy + Az, R02 = Bxz + Ay;
    const float R20 = Bxz - Ay, R12 = Byz - Ax, R21 = Byz + Ax;
    const float ox = o[3*b+0], oy = o[3*b+1], oz = o[3*b+2];
    const float dx = d[3*b+0], dy = d[3*b+1], dz = d[3*b+2];
    const long long N = n;
    float* out_no = out;          float* out_nd = out + 3*N;
    float* out_R  = out + 6*N;    float* out_t  = out + 15*N;
    out_no[3*b+0] = fmaf(R00, ox, fmaf(R01, oy, fmaf(R02, oz, tx)));
    out_no[3*b+1] = fmaf(R10, ox, fmaf(R11, oy, fmaf(R12, oz, ty)));
    out_no[3*b+2] = fmaf(R20, ox, fmaf(R21, oy, fmaf(R22, oz, tz)));
    out_nd[3*b+0] = fmaf(R00, dx, fmaf(R01, dy, R02 * dz));
    out_nd[3*b+1] = fmaf(R10, dx, fmaf(R11, dy, R12 * dz));
    out_nd[3*b+2] = fmaf(R20, dx, fmaf(R21, dy, R22 * dz));
    float* Rw = out_R + 9LL*b;
    Rw[0]=R00; Rw[1]=R01; Rw[2]=R02; Rw[3]=R10; Rw[4]=R11; Rw[5]=R12; Rw[6]=R20; Rw[7]=R21; Rw[8]=R22;
    out_t[3*b+0] = tx; out_t[3*b+1] = ty; out_t[3*b+2] = tz;
}

extern "C" void kernel_launch(void* const* d_in, const int* in_sizes, int n_in,
                              void* d_out, int out_size) {
    const int*   i_ptr = (const int*)d_in[0];
    const float* o_ptr = (const float*)d_in[1];
    const float* d_ptr = (const float*)d_in[2];
    const float* rot   = (const float*)d_in[3];
    const float* trans = (const float*)d_in[4];
    float* out = (float*)d_out;

    const int n = in_sizes[0];
    const int n_img = in_sizes[3] / 3;

    if (n_img <= MAX_SMEM_IMAGES) {
        const int rays_per_block = TPB * RAYS_PER_THREAD;
        const int blocks = (n + rays_per_block - 1) / rays_per_block;
        camx_vec_kernel<<<blocks, TPB>>>(i_ptr, o_ptr, d_ptr, rot, trans, out, n, n_img);
    } else {
        const int threads = 256;
        const int blocks = (n + threads - 1) / threads;
        camx_scalar_kernel<<<blocks, threads>>>(i_ptr, o_ptr, d_ptr, rot, trans, out, n);
    }
}